// round 1
// baseline (speedup 1.0000x reference)
#include <cuda_runtime.h>
#include <math.h>

// GroupBRouter: fused router kernel.
// logits = tokens(65536x1024) @ W_g^T(1024x64) + b_g
// probs  = softmax(logits); floor; per-batch hard cap w/ redistribution; top-2 mask.
// Shapes fixed: B=16, N=4096, D=1024, E=64, TOP_K=2.

namespace {
constexpr int D   = 1024;
constexpr int E   = 64;
constexpr int BM  = 128;   // tokens per block
constexpr int BK  = 32;    // K tile
constexpr int TPB = 128;   // threads per block
constexpr int AST = 132;   // As row stride (floats) - padded to break STS conflicts
constexpr int BST = 68;    // Bs row stride
constexpr int LST = 65;    // Ls row stride (odd -> conflict-free per-token scans)
}

__global__ __launch_bounds__(TPB)
void router_kernel(const float* __restrict__ tokens,
                   const int*   __restrict__ tsteps,
                   const float* __restrict__ Wg,
                   const float* __restrict__ bg,
                   float* __restrict__ out)
{
    // union: GEMM tiles (As 4224 + Bs 2176 floats) vs epilogue scratch (8320 floats)
    __shared__ __align__(16) float smem[BM * LST];
    float* As = smem;            // [BK][AST]  token tile, transposed (k-major)
    float* Bs = smem + BK * AST; // [BK][BST]  W tile, transposed (k-major)
    float* Ls = smem;            // [BM][LST]  per-token scratch

    const int tid  = threadIdx.x;
    const int m0   = blockIdx.x * BM;
    const int tx   = tid & 7;    // expert group 0..7  (8 experts each)
    const int ty   = tid >> 3;   // token group 0..15  (8 tokens each)
    const int colK = tx * 4;     // k sub-offset for staging loads

    float acc[8][8];
    #pragma unroll
    for (int r = 0; r < 8; ++r)
        #pragma unroll
        for (int c = 0; c < 8; ++c) acc[r][c] = 0.f;

    for (int k0 = 0; k0 < D; k0 += BK) {
        __syncthreads();   // previous iteration's readers done before overwrite
        // stage A: 128 tokens x 32 k, coalesced 128B-per-row reads, transpose to As[k][m]
        #pragma unroll
        for (int it = 0; it < 8; ++it) {
            int m = ty + it * 16;
            float4 v = *reinterpret_cast<const float4*>(
                tokens + (size_t)(m0 + m) * D + k0 + colK);
            As[(colK + 0) * AST + m] = v.x;
            As[(colK + 1) * AST + m] = v.y;
            As[(colK + 2) * AST + m] = v.z;
            As[(colK + 3) * AST + m] = v.w;
        }
        // stage B: 64 experts x 32 k (W hot in L2), transpose to Bs[k][e]
        #pragma unroll
        for (int it = 0; it < 4; ++it) {
            int e = ty + it * 16;
            float4 v = *reinterpret_cast<const float4*>(
                Wg + (size_t)e * D + k0 + colK);
            Bs[(colK + 0) * BST + e] = v.x;
            Bs[(colK + 1) * BST + e] = v.y;
            Bs[(colK + 2) * BST + e] = v.z;
            Bs[(colK + 3) * BST + e] = v.w;
        }
        __syncthreads();
        #pragma unroll 16
        for (int kk = 0; kk < BK; ++kk) {
            float4 a0 = *reinterpret_cast<const float4*>(As + kk * AST + ty * 8);
            float4 a1 = *reinterpret_cast<const float4*>(As + kk * AST + ty * 8 + 4);
            float4 b0 = *reinterpret_cast<const float4*>(Bs + kk * BST + tx * 8);
            float4 b1 = *reinterpret_cast<const float4*>(Bs + kk * BST + tx * 8 + 4);
            float a[8] = {a0.x, a0.y, a0.z, a0.w, a1.x, a1.y, a1.z, a1.w};
            float b[8] = {b0.x, b0.y, b0.z, b0.w, b1.x, b1.y, b1.z, b1.w};
            #pragma unroll
            for (int r = 0; r < 8; ++r)
                #pragma unroll
                for (int c = 0; c < 8; ++c)
                    acc[r][c] = fmaf(a[r], b[c], acc[r][c]);
        }
    }
    __syncthreads();

    // write logits (+bias) into per-token scratch
    float bv[8];
    #pragma unroll
    for (int c = 0; c < 8; ++c) bv[c] = bg[tx * 8 + c];
    #pragma unroll
    for (int r = 0; r < 8; ++r)
        #pragma unroll
        for (int c = 0; c < 8; ++c)
            Ls[(ty * 8 + r) * LST + tx * 8 + c] = acc[r][c] + bv[c];
    __syncthreads();

    // per-token epilogue: thread tid owns token (m0 + tid)
    {
        float* row = Ls + tid * LST;

        // softmax (max-subtracted, fp32)
        float mx = row[0];
        for (int j = 1; j < E; ++j) mx = fmaxf(mx, row[j]);
        float s = 0.f;
        for (int j = 0; j < E; ++j) {
            float e = expf(row[j] - mx);
            row[j] = e;
            s += e;
        }
        float inv = 1.0f / s;

        // routing floor: alpha = 0.15 -> q = 0.85*p + 0.15/64
        // hard cap: cap = 0.5 + 1.1 * t/1000 (per batch of 4096 tokens)
        int   gtok = m0 + tid;
        float tn   = (float)tsteps[gtok >> 12] / 1000.0f;
        float cap  = 0.5f + 1.1f * tn;

        float Se = 0.f, Sh = 0.f;
        for (int j = 0; j < E; ++j) {
            float q  = 0.85f * (row[j] * inv) + 0.00234375f;
            float ex = fmaxf(q - cap, 0.f);
            float cp = q - ex;
            Se += ex;
            Sh += fmaxf(cap - cp, 0.f);
            row[j] = cp;
        }
        float invSh = 1.0f / fmaxf(Sh, 1e-8f);

        // final value + top-2 scan (strict > keeps lowest index on ties, like lax.top_k)
        float v1 = -INFINITY, v2 = -INFINITY;
        int   i1 = 0, i2 = 0;
        for (int j = 0; j < E; ++j) {
            float cp = row[j];
            float f  = cp + Se * (fmaxf(cap - cp, 0.f) * invSh);
            if (f > v1)      { v2 = v1; i2 = i1; v1 = f; i1 = j; }
            else if (f > v2) { v2 = f;  i2 = j; }
        }

        // sparse gate row
        for (int j = 0; j < E; ++j) row[j] = 0.f;
        row[i1] = v1;
        row[i2] = v2;
    }
    __syncthreads();

    // coalesced store of the 128x64 gate tile
    float* ob = out + (size_t)m0 * E;
    for (int i = tid; i < BM * E; i += TPB)
        ob[i] = Ls[(i >> 6) * LST + (i & 63)];
}

extern "C" void kernel_launch(void* const* d_in, const int* in_sizes, int n_in,
                              void* d_out, int out_size)
{
    const float* tokens = nullptr;
    const int*   tarr   = nullptr;
    const float* Wg     = nullptr;
    const float* bg     = nullptr;
    for (int i = 0; i < n_in; ++i) {
        switch (in_sizes[i]) {
            case 16 * 4096 * 1024: tokens = (const float*)d_in[i]; break;
            case 16:               tarr   = (const int*)d_in[i];   break;
            case 64 * 1024:        Wg     = (const float*)d_in[i]; break;
            case 64:               bg     = (const float*)d_in[i]; break;
        }
    }
    // 65536 tokens / 128 per block = 512 blocks
    router_kernel<<<512, TPB>>>(tokens, tarr, Wg, bg, (float*)d_out);
}